// round 11
// baseline (speedup 1.0000x reference)
#include <cuda_runtime.h>
#include <cuda_bf16.h>

#define OUT_W    256
#define IMG_W    512
#define NBLK     512            // (ii in 256) x (i-half h in 2)
#define SK_T     16             // K rows per block
#define SK_W     388            // bf16x2 words per K row; 1552B = 16 mod 128
#define SREV_LEN 1032
#define OFF_K     0
#define OFF_SREV  24832         // 16*388*4
#define OFF_SREVB 26896
#define SMEM_BYTES 28960

#define NCHUNK   256            // one chunk per ii

__device__ float g_part[NCHUNK * 32 * OUT_W];   // 8 MB partials [ii][i][j]
__device__ float g_red[32 * 32 * OUT_W];        // 1 MB stage-A [seg][i][j]

__device__ __forceinline__ float frcp(float x) {
    float r; asm("rcp.approx.f32 %0, %1;" : "=f"(r) : "f"(x)); return r;
}
__device__ __forceinline__ void mma_bf16(float* d, unsigned a0, unsigned a1,
                                         unsigned a2, unsigned a3,
                                         unsigned b0, unsigned b1) {
    asm volatile(
        "mma.sync.aligned.m16n8k16.row.col.f32.bf16.bf16.f32 "
        "{%0,%1,%2,%3}, {%4,%5,%6,%7}, {%8,%9}, {%0,%1,%2,%3};"
        : "+f"(d[0]), "+f"(d[1]), "+f"(d[2]), "+f"(d[3])
        : "r"(a0), "r"(a1), "r"(a2), "r"(a3), "r"(b0), "r"(b1));
}

// ---------------------------------------------------------------------------
// Block (ii, h): one image row ii, i in [16h,16h+16). 8 warps =
// (wj: j-strip [64wj,64wj+64), 4 m-tiles) x (ni: i-octet, single n-tile).
// 36 k-steps/warp; sliding Toeplitz A window: 2 fresh A + 2 B LDS per
// 4 MMAs, explicitly double-buffered (X/Y) so LDS of step q+1 overlap
// MMAs of step q. 512 blocks, 4/SM -> one full wave, 32 warps/SM.
// ---------------------------------------------------------------------------
__global__ void __launch_bounds__(256, 4)
conv_mma_kernel(const float* __restrict__ img, const float* __restrict__ pos) {
    extern __shared__ char smem[];
    unsigned*      skw = (unsigned*)(smem + OFF_K);
    __nv_bfloat16* sr  = (__nv_bfloat16*)(smem + OFF_SREV);   // reversed row
    __nv_bfloat16* srB = (__nv_bfloat16*)(smem + OFF_SREVB);  // shifted +1

    const int ii  = blockIdx.x >> 1;
    const int h   = blockIdx.x & 1;
    const int tid = threadIdx.x;
    const float p0 = pos[0], p1 = pos[1];

    // ---- stage reversed image row (bf16): sr[z] = img[ii][767-z], z in [256,767]
    for (int z = tid; z < SREV_LEN; z += 256) {
        float v0 = (z >= 256 && z <= 767) ? img[ii * IMG_W + (767 - z)] : 0.f;
        int z1 = z + 1;
        float v1 = (z1 >= 256 && z1 <= 767) ? img[ii * IMG_W + (767 - z1)] : 0.f;
        sr [z] = __float2bfloat16_rn(v0);
        srB[z] = __float2bfloat16_rn(v1);
    }
    // ---- K rows: row t serves i = 16h + t  (d-255 = 16h + t - ii)
    for (int t = 0; t < SK_T; t++) {
        float dx  = (float)(16 * h + t - ii) + p0;
        float dx2 = dx * dx;
        for (int u = tid; u < SK_W; u += 256) {
            float dy0 = (float)(2 * u - 511) + p1;
            float dy1 = dy0 + 1.0f;
            float v0 = (2 * u     < 767) ? frcp(fmaf(dy0, dy0, dx2)) : 0.f;
            float v1 = (2 * u + 1 < 767) ? frcp(fmaf(dy1, dy1, dx2)) : 0.f;
            unsigned wv;
            asm("cvt.rn.bf16x2.f32 %0, %1, %2;" : "=r"(wv) : "f"(v1), "f"(v0));
            skw[t * SK_W + u] = wv;
        }
    }
    __syncthreads();

    const int w    = tid >> 5;
    const int wj   = w & 3;           // j strip [64wj, 64wj+64)
    const int ni   = w >> 2;          // i octet within the 16-row half
    const int lane = tid & 31;
    const int r    = lane >> 2;
    const int c    = lane & 3;
    const int sel  = r & 1;

    const unsigned* As = (const unsigned*)(sel ? srB : sr);
    const int awB = (2 * c - 64 * wj - r + 256 - sel) >> 1;
    const unsigned* pBr = skw + (8 * ni + r) * SK_W + c;

    float acc[4][4];
#pragma unroll
    for (int m = 0; m < 4; m++)
#pragma unroll
        for (int k = 0; k < 4; k++) acc[m][k] = 0.f;

#define MMAQ(W_, b0_, b1_)                                                    \
    { _Pragma("unroll")                                                       \
      for (int m = 0; m < 4; m++)                                             \
          mma_bf16(acc[m], W_[2*m+1], W_[2*m+2], W_[2*m], W_[2*m+1],          \
                   b0_, b1_); }

    // W_q[k] = As[awB + ew_q + 4 - 4k], ew_q = 32wj + 8q; slide: W_{q+1}[k] = W_q[k-2]
    unsigned WX[9], WY[9];
    unsigned bX0, bX1, bY0, bY1;
    int ew = 32 * wj;
#pragma unroll
    for (int k = 0; k < 9; k++) WX[k] = As[awB + ew + 4 - 4 * k];
    bX0 = pBr[ew]; bX1 = pBr[ew + 4];

#pragma unroll 1
    for (int it = 0; it < 17; it++) {
        // Y = step q+1
#pragma unroll
        for (int k = 2; k < 9; k++) WY[k] = WX[k - 2];
        WY[1] = As[awB + ew + 8];
        WY[0] = As[awB + ew + 12];
        bY0 = pBr[ew + 8]; bY1 = pBr[ew + 12];
        MMAQ(WX, bX0, bX1);                    // step q
        // X = step q+2
#pragma unroll
        for (int k = 2; k < 9; k++) WX[k] = WY[k - 2];
        WX[1] = As[awB + ew + 16];
        WX[0] = As[awB + ew + 20];
        bX0 = pBr[ew + 16]; bX1 = pBr[ew + 20];
        MMAQ(WY, bY0, bY1);                    // step q+1
        ew += 16;
    }
    // steps 34, 35
#pragma unroll
    for (int k = 2; k < 9; k++) WY[k] = WX[k - 2];
    WY[1] = As[awB + ew + 8];
    WY[0] = As[awB + ew + 12];
    bY0 = pBr[ew + 8]; bY1 = pBr[ew + 12];
    MMAQ(WX, bX0, bX1);
    MMAQ(WY, bY0, bY1);
#undef MMAQ

    // ---- partials: chunk ii, rows i = 16h + 8ni + 2c (+1), cols j
    float* dst = g_part + ii * (32 * OUT_W) + (16 * h + 8 * ni) * OUT_W;
#pragma unroll
    for (int m = 0; m < 4; m++) {
        const int j0 = 64 * wj + 16 * m + r;
        const int il = 2 * c;
        dst[(il    ) * OUT_W + j0    ] = acc[m][0];
        dst[(il + 1) * OUT_W + j0    ] = acc[m][1];
        dst[(il    ) * OUT_W + j0 + 8] = acc[m][2];
        dst[(il + 1) * OUT_W + j0 + 8] = acc[m][3];
    }
}

// ---------------------------------------------------------------------------
// Stage A: 65536 threads, each sums 8 of the 256 ii-chunks for one float4.
// Fully coalesced (consecutive threads -> consecutive float4). Deterministic.
// ---------------------------------------------------------------------------
__global__ void reduce_a_kernel() {
    const float4* src = (const float4*)g_part;
    const int wid = blockIdx.x * 256 + threadIdx.x;   // [0, 65536)
    const int o4  = wid & 2047;
    const int seg = wid >> 11;                        // 32 segments of 8 chunks
    float4 s = make_float4(0.f, 0.f, 0.f, 0.f);
#pragma unroll
    for (int cix = 0; cix < 8; cix++) {
        float4 v = src[(seg * 8 + cix) * 2048 + o4];
        s.x += v.x; s.y += v.y; s.z += v.z; s.w += v.w;
    }
    ((float4*)g_red)[seg * 2048 + o4] = s;
}

// ---------------------------------------------------------------------------
// Stage B: 32 blocks; block owns 64 float4 outputs x 4 workers (8 segs each),
// folded via smem in fixed order.
// ---------------------------------------------------------------------------
__global__ void reduce_b_kernel(float* __restrict__ out) {
    __shared__ float4 sred[256];
    const int t  = threadIdx.x;
    const int o4 = blockIdx.x * 64 + (t & 63);
    const int sg = t >> 6;                            // 4 workers
    const float4* src = (const float4*)g_red;
    float4 s = make_float4(0.f, 0.f, 0.f, 0.f);
#pragma unroll
    for (int k = 0; k < 8; k++) {
        float4 v = src[(sg * 8 + k) * 2048 + o4];
        s.x += v.x; s.y += v.y; s.z += v.z; s.w += v.w;
    }
    sred[t] = s;
    __syncthreads();
    if (sg == 0) {
        float4 a = sred[t];
#pragma unroll
        for (int k = 1; k < 4; k++) {
            float4 v = sred[t + 64 * k];
            a.x += v.x; a.y += v.y; a.z += v.z; a.w += v.w;
        }
        ((float4*)out)[o4] = a;
    }
}

// ---------------------------------------------------------------------------
extern "C" void kernel_launch(void* const* d_in, const int* in_sizes, int n_in,
                              void* d_out, int out_size) {
    const float* img = (const float*)d_in[0];   // [256, 512] f32
    const float* pos = (const float*)d_in[1];   // [2] f32
    float* out = (float*)d_out;                 // [32, 256] f32

    conv_mma_kernel<<<NBLK, 256, SMEM_BYTES>>>(img, pos);
    reduce_a_kernel<<<256, 256>>>();
    reduce_b_kernel<<<32, 256>>>(out);
}

// round 12
// speedup vs baseline: 1.5328x; 1.5328x over previous
#include <cuda_runtime.h>
#include <cuda_bf16.h>

#define OUT_W    256
#define IMG_W    512
#define NBLK     512            // (ii in 256) x (i-half h in 2)
#define SK_T     16             // K rows per block
#define SK_W     388            // bf16x2 words per K row; 1552B = 16 mod 128
#define SREV_W   522            // padded reversed-row length in u32 words
#define OFF_K     0
#define OFF_SREV  24832         // 16*388*4
#define OFF_SREVB 26920         // + 522*4
#define SMEM_BYTES 29008        // + 522*4

#define NCHUNK   256            // one chunk per ii

__device__ float g_part[NCHUNK * 32 * OUT_W];   // 8 MB partials [ii][i][j]
__device__ float g_red[16 * 32 * OUT_W];        // 512 KB stage-A [grp][i][j]

__device__ __forceinline__ float frcp(float x) {
    float r; asm("rcp.approx.f32 %0, %1;" : "=f"(r) : "f"(x)); return r;
}
__device__ __forceinline__ void mma_bf16(float* d, unsigned a0, unsigned a1,
                                         unsigned a2, unsigned a3,
                                         unsigned b0, unsigned b1) {
    asm volatile(
        "mma.sync.aligned.m16n8k16.row.col.f32.bf16.bf16.f32 "
        "{%0,%1,%2,%3}, {%4,%5,%6,%7}, {%8,%9}, {%0,%1,%2,%3};"
        : "+f"(d[0]), "+f"(d[1]), "+f"(d[2]), "+f"(d[3])
        : "r"(a0), "r"(a1), "r"(a2), "r"(a3), "r"(b0), "r"(b1));
}

// ---------------------------------------------------------------------------
// Block (ii, h): one image row ii, i in [16h,16h+16). 8 warps = (wj: j-strip
// [64wj,64wj+64), 4 m-tiles) x (se: e-half, 18 k-steps each). Toeplitz A
// window kept in a 16-reg ring with statically-unrolled indices: per k-step
// only 2 fresh A-LDS + 4 B-LDS + 8 MMA (no MOV slides, immediate-offset
// loads). se-halves merged in-block via SMEM -> 256 partial chunks.
// ---------------------------------------------------------------------------
__global__ void __launch_bounds__(256, 4)
conv_mma_kernel(const float* __restrict__ img, const float* __restrict__ pos) {
    extern __shared__ char smem[];
    unsigned*      skw = (unsigned*)(smem + OFF_K);
    __nv_bfloat16* sr  = (__nv_bfloat16*)(smem + OFF_SREV);   // reversed row
    __nv_bfloat16* srB = (__nv_bfloat16*)(smem + OFF_SREVB);  // shifted +1

    const int ii  = blockIdx.x >> 1;
    const int h   = blockIdx.x & 1;
    const int tid = threadIdx.x;
    const float p0 = pos[0], p1 = pos[1];

    // ---- stage reversed image row (bf16): sr[z] = img[ii][767-z], z in [256,767]
    for (int z = tid; z < 2 * SREV_W; z += 256) {
        float v0 = (z >= 256 && z <= 767) ? img[ii * IMG_W + (767 - z)] : 0.f;
        int z1 = z + 1;
        float v1 = (z1 >= 256 && z1 <= 767) ? img[ii * IMG_W + (767 - z1)] : 0.f;
        sr [z] = __float2bfloat16_rn(v0);
        srB[z] = __float2bfloat16_rn(v1);
    }
    // ---- K rows: row t serves i = 16h + t  (d-255 = 16h + t - ii)
    for (int t = 0; t < SK_T; t++) {
        float dx  = (float)(16 * h + t - ii) + p0;
        float dx2 = dx * dx;
        for (int u = tid; u < SK_W; u += 256) {
            float dy0 = (float)(2 * u - 511) + p1;
            float dy1 = dy0 + 1.0f;
            float v0 = (2 * u     < 767) ? frcp(fmaf(dy0, dy0, dx2)) : 0.f;
            float v1 = (2 * u + 1 < 767) ? frcp(fmaf(dy1, dy1, dx2)) : 0.f;
            unsigned wv;
            asm("cvt.rn.bf16x2.f32 %0, %1, %2;" : "=r"(wv) : "f"(v1), "f"(v0));
            skw[t * SK_W + u] = wv;
        }
    }
    __syncthreads();

    const int w    = tid >> 5;
    const int wj   = w & 3;           // j strip [64wj, 64wj+64)
    const int se   = w >> 2;          // e-half: k-steps q in [18se, 18se+18)
    const int lane = tid & 31;
    const int r    = lane >> 2;
    const int c    = lane & 3;
    const int sel  = r & 1;
    const int qb   = 18 * se;

    const unsigned* Asw = (const unsigned*)(sel ? srB : sr);
    const int aw0 = (2 * c - 64 * wj - r + 256 - sel) >> 1;
    const unsigned* pA0 = Asw + aw0 + 32 * wj + 8 * qb + 4;   // slot s: pA0[4s]
    const unsigned* pB0 = skw + r * SK_W + c + 32 * wj + 8 * qb;

    float acc[4][2][4];
#pragma unroll
    for (int m = 0; m < 4; m++)
#pragma unroll
        for (int n = 0; n < 2; n++)
#pragma unroll
            for (int k = 0; k < 4; k++) acc[m][n][k] = 0.f;

    // ring[(s+8) & 15] holds window slot s = 2q - k (q local step, k 0..8)
    unsigned ring[16];
#pragma unroll
    for (int t = 0; t < 9; t++) ring[t] = pA0[4 * (t - 8)];

#pragma unroll
    for (int qq = 0; qq < 18; qq++) {
        unsigned bb0 = pB0[8 * qq],            bb1 = pB0[8 * qq + 4];
        unsigned bb2 = pB0[8 * SK_W + 8 * qq], bb3 = pB0[8 * SK_W + 8 * qq + 4];
        // prefetch slots 2qq+1, 2qq+2 (used from step qq+1 on; disjoint mod 16)
        ring[(2 * qq + 9)  & 15] = pA0[4 * (2 * qq + 1)];
        ring[(2 * qq + 10) & 15] = pA0[4 * (2 * qq + 2)];
#pragma unroll
        for (int m = 0; m < 4; m++) {
            unsigned a0 = ring[(2 * qq - 2 * m + 7) & 15];   // W[2m+1]
            unsigned a1 = ring[(2 * qq - 2 * m + 6) & 15];   // W[2m+2]
            unsigned a2 = ring[(2 * qq - 2 * m + 8) & 15];   // W[2m]
            mma_bf16(acc[m][0], a0, a1, a2, a0, bb0, bb1);
            mma_bf16(acc[m][1], a0, a1, a2, a0, bb2, bb3);
        }
    }

    // ---- merge e-halves in-block (skw region is dead after this sync) ----
    float* mbuf = (float*)smem;       // [wj][32 idx][32 lanes] = 16 KB
    __syncthreads();
    if (se == 1) {
        float* bp = mbuf + wj * 1024 + lane;
#pragma unroll
        for (int m = 0; m < 4; m++)
#pragma unroll
            for (int n = 0; n < 2; n++)
#pragma unroll
                for (int k = 0; k < 4; k++)
                    bp[(((m * 2 + n) * 4) + k) * 32] = acc[m][n][k];
    }
    __syncthreads();
    if (se == 0) {
        const float* bp = mbuf + wj * 1024 + lane;
        float* dst = g_part + ii * (32 * OUT_W) + (16 * h) * OUT_W;
#pragma unroll
        for (int m = 0; m < 4; m++) {
            const int j0 = 64 * wj + 16 * m + r;
#pragma unroll
            for (int nn = 0; nn < 2; nn++) {
                const int il = 8 * nn + 2 * c;
                float v0 = acc[m][nn][0] + bp[(((m*2+nn)*4) + 0) * 32];
                float v1 = acc[m][nn][1] + bp[(((m*2+nn)*4) + 1) * 32];
                float v2 = acc[m][nn][2] + bp[(((m*2+nn)*4) + 2) * 32];
                float v3 = acc[m][nn][3] + bp[(((m*2+nn)*4) + 3) * 32];
                dst[(il    ) * OUT_W + j0    ] = v0;
                dst[(il + 1) * OUT_W + j0    ] = v1;
                dst[(il    ) * OUT_W + j0 + 8] = v2;
                dst[(il + 1) * OUT_W + j0 + 8] = v3;
            }
        }
    }
}

// ---------------------------------------------------------------------------
// R6-shaped two-stage deterministic reduction over 256 chunks.
// ---------------------------------------------------------------------------
__global__ void reduce_a_kernel() {
    const int g  = blockIdx.x >> 5;                  // 16 groups of 16 chunks
    const int o  = (blockIdx.x & 31) * 256 + threadIdx.x;
    const int c0 = g * 16;
    float s0 = 0.f, s1 = 0.f, s2 = 0.f, s3 = 0.f;
#pragma unroll
    for (int c = 0; c < 16; c += 4) {
        s0 += g_part[(c0 + c + 0) * 8192 + o];
        s1 += g_part[(c0 + c + 1) * 8192 + o];
        s2 += g_part[(c0 + c + 2) * 8192 + o];
        s3 += g_part[(c0 + c + 3) * 8192 + o];
    }
    g_red[g * 8192 + o] = (s0 + s1) + (s2 + s3);
}

__global__ void reduce_b_kernel(float* __restrict__ out) {
    const int o = blockIdx.x * 256 + threadIdx.x;
    float s = 0.f;
#pragma unroll
    for (int g = 0; g < 16; g++) s += g_red[g * 8192 + o];
    out[o] = s;
}

// ---------------------------------------------------------------------------
extern "C" void kernel_launch(void* const* d_in, const int* in_sizes, int n_in,
                              void* d_out, int out_size) {
    const float* img = (const float*)d_in[0];   // [256, 512] f32
    const float* pos = (const float*)d_in[1];   // [2] f32
    float* out = (float*)d_out;                 // [32, 256] f32

    conv_mma_kernel<<<NBLK, 256, SMEM_BYTES>>>(img, pos);
    reduce_a_kernel<<<512, 256>>>();
    reduce_b_kernel<<<32, 256>>>(out);
}